// round 3
// baseline (speedup 1.0000x reference)
#include <cuda_runtime.h>
#include <math.h>

#define HDIM 256
#define MAXN 32768
#define BK 16
#define GBM 128
#define GBN 32

// Scratch (allocations are forbidden; __device__ globals are the sanctioned path)
__device__ float g_hA[(size_t)MAXN * HDIM];
__device__ float g_hB[(size_t)MAXN * HDIM];
__device__ float g_din[(size_t)MAXN * HDIM];

// Packed f32x2 FMA: d.lo += a.lo*b.lo ; d.hi += a.hi*b.hi  (Blackwell f32x2 pipe)
__device__ __forceinline__ void ffma2(unsigned long long& d, unsigned long long a,
                                      unsigned long long b) {
    asm("fma.rn.f32x2 %0, %1, %2, %0;" : "+l"(d) : "l"(a), "l"(b));
}
__device__ __forceinline__ float lo32(unsigned long long v) {
    return __uint_as_float((unsigned int)v);
}
__device__ __forceinline__ float hi32(unsigned long long v) {
    return __uint_as_float((unsigned int)(v >> 32));
}
__device__ __forceinline__ unsigned long long dup2(float v) {
    unsigned int u = __float_as_uint(v);
    return ((unsigned long long)u << 32) | u;
}

__device__ __forceinline__ float sigm(float v) {
    return 1.0f / (1.0f + __expf(-v));
}
__device__ __forceinline__ float tanh_fast(float x) {
    x = fminf(fmaxf(x, -10.0f), 10.0f);
    float e = __expf(2.0f * x);
    return __fdividef(e - 1.0f, e + 1.0f);
}

// ---------------------------------------------------------------------------
// Fused GRU step: hnew = GRUCell(e, hprev)
//   EMBED=true : e = relu(x[:,t,:] @ embW.T + embB)   (input dim 4, fused)
//   EMBED=false: e = xin (a [N,HDIM] buffer)
// Gate order (PyTorch): r = [0,H), z = [H,2H), n = [2H,3H)
// Accumulators per output (m,j):
//   sr = e@Wih_r + h@Whh_r ; sz = e@Wih_z + h@Whh_z
//   si = e@Wih_n           ; sh = h@Whh_n            (separate: n needs r*hn)
// ---------------------------------------------------------------------------
template <bool EMBED>
__global__ __launch_bounds__(256, 2)
void gru_kernel(const float* __restrict__ xin, int t, int T,
                const float* __restrict__ embW, const float* __restrict__ embB,
                const float* __restrict__ hprev,
                const float* __restrict__ Wih, const float* __restrict__ Whh,
                const float* __restrict__ bih, const float* __restrict__ bhh,
                float* __restrict__ hnew, int N)
{
    __shared__ float Es[BK][GBM + 4];          // e tile, k-major
    __shared__ float Hs[BK][GBM + 4];          // h tile, k-major
    __shared__ float Wd[6][BK][2 * GBN + 4];   // weights, each value DUPLICATED (pair)

    const int tid = threadIdx.x;
    const int tx  = tid & 15;    // column group (2 cols)
    const int ty  = tid >> 4;    // row group (8 rows)
    const int M0  = blockIdx.x * GBM;
    const int J0  = blockIdx.y * GBN;

    unsigned long long sr[4][2], sz[4][2], si[4][2], sh[4][2];
#pragma unroll
    for (int p = 0; p < 4; p++)
#pragma unroll
        for (int c = 0; c < 2; c++) { sr[p][c] = 0ull; sz[p][c] = 0ull; si[p][c] = 0ull; sh[p][c] = 0ull; }

    float4 xv = make_float4(0.f, 0.f, 0.f, 0.f);
    if (EMBED) {
        int m = M0 + (tid & 127);
        if (m < N) xv = *(const float4*)(xin + ((size_t)m * T + t) * 4);
    }

    const int wj = tid >> 3;   // 0..31  (output column within tile)
    const int wq = tid & 7;    // 0..7   (k pair index)

    for (int k0 = 0; k0 < HDIM; k0 += BK) {
        // --- load 6 weight tiles, duplicated per value for f32x2 broadcast ---
#pragma unroll
        for (int g = 0; g < 3; g++) {
            float2 vi = *(const float2*)(Wih + (size_t)(g * HDIM + J0 + wj) * HDIM + k0 + 2 * wq);
            *(unsigned long long*)&Wd[g][2 * wq    ][2 * wj] = dup2(vi.x);
            *(unsigned long long*)&Wd[g][2 * wq + 1][2 * wj] = dup2(vi.y);
            float2 vh = *(const float2*)(Whh + (size_t)(g * HDIM + J0 + wj) * HDIM + k0 + 2 * wq);
            *(unsigned long long*)&Wd[3 + g][2 * wq    ][2 * wj] = dup2(vh.x);
            *(unsigned long long*)&Wd[3 + g][2 * wq + 1][2 * wj] = dup2(vh.y);
        }
        // --- load h tile (transpose to k-major) ---
#pragma unroll
        for (int it = 0; it < 2; it++) {
            int idx = tid + it * 256;       // 0..511 float4 slots
            int m = idx >> 2, q = idx & 3;
            int mg = M0 + m;
            float4 v = make_float4(0.f, 0.f, 0.f, 0.f);
            if (mg < N) v = *(const float4*)(hprev + (size_t)mg * HDIM + k0 + 4 * q);
            Hs[4 * q + 0][m] = v.x; Hs[4 * q + 1][m] = v.y;
            Hs[4 * q + 2][m] = v.z; Hs[4 * q + 3][m] = v.w;
        }
        // --- load / compute e tile ---
        if (EMBED) {
            int m  = tid & 127;
            int kb = tid >> 7;  // 0..1
#pragma unroll
            for (int i = 0; i < 8; i++) {
                int kk = kb + 2 * i;
                int k  = k0 + kk;
                float4 w = *(const float4*)(embW + (size_t)k * 4);
                float e = xv.x * w.x + xv.y * w.y + xv.z * w.z + xv.w * w.w + embB[k];
                Es[kk][m] = fmaxf(e, 0.0f);
            }
        } else {
#pragma unroll
            for (int it = 0; it < 2; it++) {
                int idx = tid + it * 256;
                int m = idx >> 2, q = idx & 3;
                int mg = M0 + m;
                float4 v = make_float4(0.f, 0.f, 0.f, 0.f);
                if (mg < N) v = *(const float4*)(xin + (size_t)mg * HDIM + k0 + 4 * q);
                Es[4 * q + 0][m] = v.x; Es[4 * q + 1][m] = v.y;
                Es[4 * q + 2][m] = v.z; Es[4 * q + 3][m] = v.w;
            }
        }
        __syncthreads();

        // --- compute: 48 packed FMA2 per k (16 independent accumulator chains) ---
#pragma unroll
        for (int k = 0; k < BK; k++) {
            ulonglong2 eA = *(const ulonglong2*)&Es[k][ty * 8];
            ulonglong2 eB = *(const ulonglong2*)&Es[k][ty * 8 + 4];
            ulonglong2 hA = *(const ulonglong2*)&Hs[k][ty * 8];
            ulonglong2 hB = *(const ulonglong2*)&Hs[k][ty * 8 + 4];
            unsigned long long e[4] = {eA.x, eA.y, eB.x, eB.y};
            unsigned long long h[4] = {hA.x, hA.y, hB.x, hB.y};
            ulonglong2 wri = *(const ulonglong2*)&Wd[0][k][4 * tx];
            ulonglong2 wzi = *(const ulonglong2*)&Wd[1][k][4 * tx];
            ulonglong2 wni = *(const ulonglong2*)&Wd[2][k][4 * tx];
            ulonglong2 wrh = *(const ulonglong2*)&Wd[3][k][4 * tx];
            ulonglong2 wzh = *(const ulonglong2*)&Wd[4][k][4 * tx];
            ulonglong2 wnh = *(const ulonglong2*)&Wd[5][k][4 * tx];
#pragma unroll
            for (int p = 0; p < 4; p++) {
                ffma2(sr[p][0], e[p], wri.x); ffma2(sr[p][0], h[p], wrh.x);
                ffma2(sr[p][1], e[p], wri.y); ffma2(sr[p][1], h[p], wrh.y);
                ffma2(sz[p][0], e[p], wzi.x); ffma2(sz[p][0], h[p], wzh.x);
                ffma2(sz[p][1], e[p], wzi.y); ffma2(sz[p][1], h[p], wzh.y);
                ffma2(si[p][0], e[p], wni.x);
                ffma2(si[p][1], e[p], wni.y);
                ffma2(sh[p][0], h[p], wnh.x);
                ffma2(sh[p][1], h[p], wnh.y);
            }
        }
        __syncthreads();
    }

    // --- epilogue: gates + blend ---
#pragma unroll
    for (int c = 0; c < 2; c++) {
        int j = J0 + tx * 2 + c;
        float br  = bih[j] + bhh[j];
        float bz  = bih[HDIM + j] + bhh[HDIM + j];
        float bin = bih[2 * HDIM + j];
        float bhn = bhh[2 * HDIM + j];
#pragma unroll
        for (int p = 0; p < 4; p++) {
            int m0 = M0 + ty * 8 + 2 * p;
#pragma unroll
            for (int e2 = 0; e2 < 2; e2++) {
                int m = m0 + e2;
                if (m < N) {
                    float vr = e2 ? hi32(sr[p][c]) : lo32(sr[p][c]);
                    float vz = e2 ? hi32(sz[p][c]) : lo32(sz[p][c]);
                    float vi = e2 ? hi32(si[p][c]) : lo32(si[p][c]);
                    float vh = e2 ? hi32(sh[p][c]) : lo32(sh[p][c]);
                    float hold = hprev[(size_t)m * HDIM + j];
                    float r = sigm(vr + br);
                    float z = sigm(vz + bz);
                    float n = tanh_fast(vi + bin + r * (vh + bhn));
                    hnew[(size_t)m * HDIM + j] = (1.0f - z) * n + z * hold;
                }
            }
        }
    }
}

// ---------------------------------------------------------------------------
// dec_in = relu(h @ W.T + b)   (W is [HDIM, HDIM] row-major)
// ---------------------------------------------------------------------------
__global__ __launch_bounds__(256, 2)
void linear_relu_kernel(const float* __restrict__ hin, const float* __restrict__ W,
                        const float* __restrict__ b, float* __restrict__ outp, int N)
{
    __shared__ float Hs[BK][GBM + 4];
    __shared__ float Wd[BK][2 * GBN + 4];

    const int tid = threadIdx.x;
    const int tx  = tid & 15;
    const int ty  = tid >> 4;
    const int M0  = blockIdx.x * GBM;
    const int J0  = blockIdx.y * GBN;

    unsigned long long acc[4][2];
#pragma unroll
    for (int p = 0; p < 4; p++) { acc[p][0] = 0ull; acc[p][1] = 0ull; }

    const int wj = tid >> 3;
    const int wq = tid & 7;

    for (int k0 = 0; k0 < HDIM; k0 += BK) {
        {
            float2 v = *(const float2*)(W + (size_t)(J0 + wj) * HDIM + k0 + 2 * wq);
            *(unsigned long long*)&Wd[2 * wq    ][2 * wj] = dup2(v.x);
            *(unsigned long long*)&Wd[2 * wq + 1][2 * wj] = dup2(v.y);
        }
#pragma unroll
        for (int it = 0; it < 2; it++) {
            int idx = tid + it * 256;
            int m = idx >> 2, q = idx & 3;
            int mg = M0 + m;
            float4 v = make_float4(0.f, 0.f, 0.f, 0.f);
            if (mg < N) v = *(const float4*)(hin + (size_t)mg * HDIM + k0 + 4 * q);
            Hs[4 * q + 0][m] = v.x; Hs[4 * q + 1][m] = v.y;
            Hs[4 * q + 2][m] = v.z; Hs[4 * q + 3][m] = v.w;
        }
        __syncthreads();
#pragma unroll
        for (int k = 0; k < BK; k++) {
            ulonglong2 hA2 = *(const ulonglong2*)&Hs[k][ty * 8];
            ulonglong2 hB2 = *(const ulonglong2*)&Hs[k][ty * 8 + 4];
            unsigned long long h[4] = {hA2.x, hA2.y, hB2.x, hB2.y};
            ulonglong2 w = *(const ulonglong2*)&Wd[k][4 * tx];
#pragma unroll
            for (int p = 0; p < 4; p++) {
                ffma2(acc[p][0], h[p], w.x);
                ffma2(acc[p][1], h[p], w.y);
            }
        }
        __syncthreads();
    }
#pragma unroll
    for (int c = 0; c < 2; c++) {
        int j = J0 + tx * 2 + c;
        float bj = b[j];
#pragma unroll
        for (int p = 0; p < 4; p++) {
            int m0 = M0 + ty * 8 + 2 * p;
            if (m0 < N)     outp[(size_t)m0 * HDIM + j]       = fmaxf(lo32(acc[p][c]) + bj, 0.f);
            if (m0 + 1 < N) outp[(size_t)(m0 + 1) * HDIM + j] = fmaxf(hi32(acc[p][c]) + bj, 0.f);
        }
    }
}

// ---------------------------------------------------------------------------
// y[:, t, :] = h @ out_W.T + out_b    (4 output features; one warp per row)
// ---------------------------------------------------------------------------
__global__ void out_proj_kernel(const float* __restrict__ hin, const float* __restrict__ oW,
                                const float* __restrict__ ob, float* __restrict__ y,
                                int t, int PL, int N)
{
    int row  = blockIdx.x * 8 + (threadIdx.x >> 5);
    int lane = threadIdx.x & 31;
    if (row >= N) return;
    const float* hr = hin + (size_t)row * HDIM;
    float a0 = 0.f, a1 = 0.f, a2 = 0.f, a3 = 0.f;
#pragma unroll
    for (int k = lane; k < HDIM; k += 32) {
        float hv = hr[k];
        a0 += hv * oW[k];
        a1 += hv * oW[HDIM + k];
        a2 += hv * oW[2 * HDIM + k];
        a3 += hv * oW[3 * HDIM + k];
    }
#pragma unroll
    for (int off = 16; off > 0; off >>= 1) {
        a0 += __shfl_down_sync(0xffffffffu, a0, off);
        a1 += __shfl_down_sync(0xffffffffu, a1, off);
        a2 += __shfl_down_sync(0xffffffffu, a2, off);
        a3 += __shfl_down_sync(0xffffffffu, a3, off);
    }
    if (lane == 0) {
        float4 r = make_float4(a0 + ob[0], a1 + ob[1], a2 + ob[2], a3 + ob[3]);
        *(float4*)(y + ((size_t)row * PL + t) * 4) = r;
    }
}

// ---------------------------------------------------------------------------
extern "C" void kernel_launch(void* const* d_in, const int* in_sizes, int n_in,
                              void* d_out, int out_size)
{
    const float* x    = (const float*)d_in[0];
    const float* embW = (const float*)d_in[1];
    const float* embB = (const float*)d_in[2];
    const float* eWih = (const float*)d_in[3];
    const float* eWhh = (const float*)d_in[4];
    const float* eBih = (const float*)d_in[5];
    const float* eBhh = (const float*)d_in[6];
    const float* dEW  = (const float*)d_in[7];
    const float* dEB  = (const float*)d_in[8];
    const float* dWih = (const float*)d_in[9];
    const float* dWhh = (const float*)d_in[10];
    const float* dBih = (const float*)d_in[11];
    const float* dBhh = (const float*)d_in[12];
    const float* oW   = (const float*)d_in[13];
    const float* oB   = (const float*)d_in[14];

    const int T = 15;
    int N = in_sizes[0] / (T * 4);
    if (N > MAXN) N = MAXN;
    int PL = out_size / (N * 4);
    float* y = (float*)d_out;

    float *hA, *hB, *din;
    cudaGetSymbolAddress((void**)&hA, g_hA);
    cudaGetSymbolAddress((void**)&hB, g_hB);
    cudaGetSymbolAddress((void**)&din, g_din);

    dim3 gGrid((N + GBM - 1) / GBM, HDIM / GBN);
    dim3 blk(256);

    // h0 = 0 (graph-capturable async memset; no allocations)
    cudaMemsetAsync(hA, 0, (size_t)N * HDIM * sizeof(float));

    float* hc = hA;
    float* hn = hB;
    for (int t = 0; t < T; t++) {
        gru_kernel<true><<<gGrid, blk>>>(x, t, T, embW, embB, hc,
                                         eWih, eWhh, eBih, eBhh, hn, N);
        float* tmp = hc; hc = hn; hn = tmp;
    }
    linear_relu_kernel<<<gGrid, blk>>>(hc, dEW, dEB, din, N);
    for (int t = 0; t < PL; t++) {
        gru_kernel<false><<<gGrid, blk>>>(din, 0, 0, (const float*)0, (const float*)0, hc,
                                          dWih, dWhh, dBih, dBhh, hn, N);
        float* tmp = hc; hc = hn; hn = tmp;
        out_proj_kernel<<<(N + 7) / 8, 256>>>(hc, oW, oB, y, t, PL, N);
        if (t + 1 < PL) linear_relu_kernel<<<gGrid, blk>>>(hc, dEW, dEB, din, N);
    }
}

// round 7
// speedup vs baseline: 1.0261x; 1.0261x over previous
#include <cuda_runtime.h>
#include <math.h>

#define H 256
#define MAXN 32768
#define BK 8
#define RP 260            // padded row length for Es/Hs (floats)

// ---------------- scratch (__device__ globals; allocs forbidden) ----------
__device__ float g_hA[(size_t)MAXN * H];
__device__ float g_hB[(size_t)MAXN * H];
__device__ float g_din[(size_t)MAXN * H];
// packed weights: [jt][k][g][j']  (g: 0..2 = Wih r,z,n ; 3..5 = Whh r,z,n)
__device__ float g_packE[8 * 256 * 192];
__device__ float g_packD[8 * 256 * 192];
// packed dec_embed: [jt][k][j']  (4 tiles of 64 cols)
__device__ float g_packL[4 * 256 * 64];

// ---------------- helpers -------------------------------------------------
__device__ __forceinline__ void ffma2(unsigned long long& d, unsigned long long a,
                                      unsigned long long b) {
    asm("fma.rn.f32x2 %0, %1, %2, %0;" : "+l"(d) : "l"(a), "l"(b));
}
__device__ __forceinline__ unsigned long long dup2(float v) {
    unsigned long long r;
    asm("mov.b64 %0, {%1, %1};" : "=l"(r) : "f"(v));
    return r;
}
__device__ __forceinline__ float lo32(unsigned long long v) {
    return __uint_as_float((unsigned int)v);
}
__device__ __forceinline__ float hi32(unsigned long long v) {
    return __uint_as_float((unsigned int)(v >> 32));
}
__device__ __forceinline__ float sigm(float v) { return 1.0f / (1.0f + __expf(-v)); }
__device__ __forceinline__ float tanh_fast(float x) {
    x = fminf(fmaxf(x, -10.0f), 10.0f);
    float e = __expf(2.0f * x);
    return __fdividef(e - 1.0f, e + 1.0f);
}

// ---------------- weight pre-pack (runs once per launch) ------------------
__global__ void pack_kernel(const float* __restrict__ eWih, const float* __restrict__ eWhh,
                            const float* __restrict__ dWih, const float* __restrict__ dWhh,
                            const float* __restrict__ dEW) {
    int i = blockIdx.x * 256 + threadIdx.x;
    const int NP = 8 * 256 * 192;
    if (i < NP) {
        int jt = i / (256 * 192);
        int r  = i % (256 * 192);
        int k  = r / 192;
        int g  = (r % 192) / 32;
        int j  = r % 32;
        int row = jt * 32 + j;
        g_packE[i] = (g < 3) ? eWih[((size_t)(g * H + row)) * H + k]
                             : eWhh[((size_t)((g - 3) * H + row)) * H + k];
        g_packD[i] = (g < 3) ? dWih[((size_t)(g * H + row)) * H + k]
                             : dWhh[((size_t)((g - 3) * H + row)) * H + k];
    } else {
        int t = i - NP;
        if (t < 4 * 256 * 64) {
            int jt = t / (256 * 64);
            int r  = t % (256 * 64);
            int k  = r / 64;
            int j  = r % 64;
            g_packL[t] = dEW[((size_t)(jt * 64 + j)) * H + k];
        }
    }
}

// ---------------------------------------------------------------------------
// GRU step, v2.  CTA tile: 256 rows x 32 cols. Thread: 8 rows x 2 col-pairs.
// All 6 weight matrices for this j-tile live in smem for the whole kernel.
// f32x2 pairs run over adjacent COLUMNS -> weights need no duplication.
// ---------------------------------------------------------------------------
template <bool EMBED>
__global__ __launch_bounds__(256, 1)
void gru2(const float* __restrict__ xin, int t,
          const float* __restrict__ embW, const float* __restrict__ embB,
          const float* __restrict__ hprev,
          const float* __restrict__ packW,
          const float* __restrict__ bih, const float* __restrict__ bhh,
          float* __restrict__ hnew, int N)
{
    extern __shared__ float sm[];
    float* Es = sm;                    // [BK][RP]
    float* Hs = sm + BK * RP;          // [BK][RP]
    float* Ws = sm + 2 * BK * RP;      // [256][6][32] = 49152 floats

    const int tid = threadIdx.x;
    const int tx  = tid & 7;           // col-pair base (cols 2tx.. / 2tx+16..)
    const int ty  = tid >> 3;          // row group (8 rows)
    const int M0  = blockIdx.x * 256;
    const int J0  = blockIdx.y * 32;

    // fill mapping: (fm row, fq float4-k-chunk); lanes -> consecutive fm
    const int fq = (tid >> 6) & 1;                      // 0..1 -> k offset 4*fq
    const int fm = (tid & 63) | ((tid >> 7) << 6);      // 0..127

    unsigned long long sr[8][2], sz[8][2], si[8][2], sh[8][2];
#pragma unroll
    for (int r = 0; r < 8; r++)
#pragma unroll
        for (int c = 0; c < 2; c++) { sr[r][c] = 0ull; sz[r][c] = 0ull; si[r][c] = 0ull; sh[r][c] = 0ull; }

    float4 xv = make_float4(0.f, 0.f, 0.f, 0.f);
    if (EMBED) {
        int m = M0 + tid;
        if (m < N) xv = *(const float4*)(xin + ((size_t)m * 15 + t) * 4);
    }

    // prologue: prefetch k-tile 0 of h (and e) into registers
    float4 hp0, hp1, ep0, ep1;
    {
        int m0 = M0 + fm, m1 = M0 + fm + 128;
        hp0 = (m0 < N) ? *(const float4*)(hprev + (size_t)m0 * H + 4 * fq) : make_float4(0, 0, 0, 0);
        hp1 = (m1 < N) ? *(const float4*)(hprev + (size_t)m1 * H + 4 * fq) : make_float4(0, 0, 0, 0);
        if (!EMBED) {
            ep0 = (m0 < N) ? *(const float4*)(xin + (size_t)m0 * H + 4 * fq) : make_float4(0, 0, 0, 0);
            ep1 = (m1 < N) ? *(const float4*)(xin + (size_t)m1 * H + 4 * fq) : make_float4(0, 0, 0, 0);
        }
    }

    // stage all weights for this j-tile into smem (coalesced, once)
    {
        const float4* src = (const float4*)(packW + (size_t)blockIdx.y * (256 * 192));
        float4* dst = (float4*)Ws;
#pragma unroll
        for (int i = 0; i < 48; i++) dst[tid + i * 256] = src[tid + i * 256];
    }

    for (int it = 0; it < 32; it++) {
        // ---- store staged tile ----
        {
            int r0 = 4 * fq;
            Hs[(r0 + 0) * RP + fm] = hp0.x; Hs[(r0 + 1) * RP + fm] = hp0.y;
            Hs[(r0 + 2) * RP + fm] = hp0.z; Hs[(r0 + 3) * RP + fm] = hp0.w;
            Hs[(r0 + 0) * RP + fm + 128] = hp1.x; Hs[(r0 + 1) * RP + fm + 128] = hp1.y;
            Hs[(r0 + 2) * RP + fm + 128] = hp1.z; Hs[(r0 + 3) * RP + fm + 128] = hp1.w;
            if (EMBED) {
                int k0 = it * BK;
#pragma unroll
                for (int kk = 0; kk < BK; kk++) {
                    int k = k0 + kk;
                    float4 w = __ldg((const float4*)(embW + (size_t)k * 4));
                    float e = xv.x * w.x + xv.y * w.y + xv.z * w.z + xv.w * w.w + __ldg(embB + k);
                    Es[kk * RP + tid] = fmaxf(e, 0.0f);
                }
            } else {
                int r1 = 4 * fq;
                Es[(r1 + 0) * RP + fm] = ep0.x; Es[(r1 + 1) * RP + fm] = ep0.y;
                Es[(r1 + 2) * RP + fm] = ep0.z; Es[(r1 + 3) * RP + fm] = ep0.w;
                Es[(r1 + 0) * RP + fm + 128] = ep1.x; Es[(r1 + 1) * RP + fm + 128] = ep1.y;
                Es[(r1 + 2) * RP + fm + 128] = ep1.z; Es[(r1 + 3) * RP + fm + 128] = ep1.w;
            }
        }
        __syncthreads();

        // ---- prefetch next tile (overlaps compute) ----
        if (it + 1 < 32) {
            int k0n = (it + 1) * BK;
            int m0 = M0 + fm, m1 = M0 + fm + 128;
            hp0 = (m0 < N) ? *(const float4*)(hprev + (size_t)m0 * H + k0n + 4 * fq) : make_float4(0, 0, 0, 0);
            hp1 = (m1 < N) ? *(const float4*)(hprev + (size_t)m1 * H + k0n + 4 * fq) : make_float4(0, 0, 0, 0);
            if (!EMBED) {
                ep0 = (m0 < N) ? *(const float4*)(xin + (size_t)m0 * H + k0n + 4 * fq) : make_float4(0, 0, 0, 0);
                ep1 = (m1 < N) ? *(const float4*)(xin + (size_t)m1 * H + k0n + 4 * fq) : make_float4(0, 0, 0, 0);
            }
        }

        // ---- compute ----
        const float* wkbase = Ws + (size_t)it * BK * 192;
#pragma unroll
        for (int kk = 0; kk < BK; kk++) {
            const float* ebase = Es + kk * RP + ty * 8;
            const float* hbase = Hs + kk * RP + ty * 8;
            float4 ea = *(const float4*)ebase;
            float4 eb = *(const float4*)(ebase + 4);
            float4 ha = *(const float4*)hbase;
            float4 hb = *(const float4*)(hbase + 4);
            const float* w = wkbase + kk * 192;
            unsigned long long w0[6], w1[6];
#pragma unroll
            for (int g = 0; g < 6; g++) {
                w0[g] = *(const unsigned long long*)(w + g * 32 + 2 * tx);
                w1[g] = *(const unsigned long long*)(w + g * 32 + 16 + 2 * tx);
            }
            float ev[8] = {ea.x, ea.y, ea.z, ea.w, eb.x, eb.y, eb.z, eb.w};
            float hv[8] = {ha.x, ha.y, ha.z, ha.w, hb.x, hb.y, hb.z, hb.w};
#pragma unroll
            for (int r = 0; r < 8; r++) {
                unsigned long long ed = dup2(ev[r]);
                unsigned long long hd = dup2(hv[r]);
                ffma2(sr[r][0], ed, w0[0]); ffma2(sr[r][0], hd, w0[3]);
                ffma2(sz[r][0], ed, w0[1]); ffma2(sz[r][0], hd, w0[4]);
                ffma2(si[r][0], ed, w0[2]); ffma2(sh[r][0], hd, w0[5]);
                ffma2(sr[r][1], ed, w1[0]); ffma2(sr[r][1], hd, w1[3]);
                ffma2(sz[r][1], ed, w1[1]); ffma2(sz[r][1], hd, w1[4]);
                ffma2(si[r][1], ed, w1[2]); ffma2(sh[r][1], hd, w1[5]);
            }
        }
        __syncthreads();
    }

    // ---- epilogue: gates + blend ----
#pragma unroll
    for (int cp = 0; cp < 2; cp++) {
        int jb = J0 + 2 * tx + cp * 16;
        float brx = bih[jb] + bhh[jb],               bry = bih[jb + 1] + bhh[jb + 1];
        float bzx = bih[H + jb] + bhh[H + jb],       bzy = bih[H + jb + 1] + bhh[H + jb + 1];
        float bix = bih[2 * H + jb],                 biy = bih[2 * H + jb + 1];
        float bhx = bhh[2 * H + jb],                 bhy = bhh[2 * H + jb + 1];
#pragma unroll
        for (int r = 0; r < 8; r++) {
            int m = M0 + ty * 8 + r;
            if (m < N) {
                float2 hold = *(const float2*)(hprev + (size_t)m * H + jb);
                float rx = sigm(lo32(sr[r][cp]) + brx);
                float ry = sigm(hi32(sr[r][cp]) + bry);
                float zx = sigm(lo32(sz[r][cp]) + bzx);
                float zy = sigm(hi32(sz[r][cp]) + bzy);
                float nx = tanh_fast(lo32(si[r][cp]) + bix + rx * (lo32(sh[r][cp]) + bhx));
                float ny = tanh_fast(hi32(si[r][cp]) + biy + ry * (hi32(sh[r][cp]) + bhy));
                float2 o;
                o.x = (1.0f - zx) * nx + zx * hold.x;
                o.y = (1.0f - zy) * ny + zy * hold.y;
                *(float2*)(hnew + (size_t)m * H + jb) = o;
            }
        }
    }
}

// ---------------------------------------------------------------------------
// dec_in = relu(h @ W.T + b), v2. CTA: 256 rows x 64 cols; thread: 8 x 4 cps.
// ---------------------------------------------------------------------------
__global__ __launch_bounds__(256, 2)
void lin2(const float* __restrict__ hin, const float* __restrict__ packL,
          const float* __restrict__ b, float* __restrict__ outp, int N)
{
    extern __shared__ float sm[];
    float* Hs = sm;                    // [BK][RP]
    float* Ws = sm + BK * RP;          // [256][64]

    const int tid = threadIdx.x;
    const int tx  = tid & 7;
    const int ty  = tid >> 3;
    const int M0  = blockIdx.x * 256;
    const int J0  = blockIdx.y * 64;

    const int fq = (tid >> 6) & 1;
    const int fm = (tid & 63) | ((tid >> 7) << 6);

    unsigned long long acc[8][4];
#pragma unroll
    for (int r = 0; r < 8; r++)
#pragma unroll
        for (int s = 0; s < 4; s++) acc[r][s] = 0ull;

    float4 hp0, hp1;
    {
        int m0 = M0 + fm, m1 = M0 + fm + 128;
        hp0 = (m0 < N) ? *(const float4*)(hin + (size_t)m0 * H + 4 * fq) : make_float4(0, 0, 0, 0);
        hp1 = (m1 < N) ? *(const float4*)(hin + (size_t)m1 * H + 4 * fq) : make_float4(0, 0, 0, 0);
    }
    {
        const float4* src = (const float4*)(packL + (size_t)blockIdx.y * (256 * 64));
        float4* dst = (float4*)Ws;
#pragma unroll
        for (int i = 0; i < 16; i++) dst[tid + i * 256] = src[tid + i * 256];
    }

    for (int it = 0; it < 32; it++) {
        {
            int r0 = 4 * fq;
            Hs[(r0 + 0) * RP + fm] = hp0.x; Hs[(r0 + 1) * RP + fm] = hp0.y;
            Hs[(r0 + 2) * RP + fm] = hp0.z; Hs[(r0 + 3) * RP + fm] = hp0.w;
            Hs[(r0 + 0) * RP + fm + 128] = hp1.x; Hs[(r0 + 1) * RP + fm + 128] = hp1.y;
            Hs[(r0 + 2) * RP + fm + 128] = hp1.z; Hs[(r0 + 3) * RP + fm + 128] = hp1.w;
        }
        __syncthreads();
        if (it + 1 < 32) {
            int k0n = (it + 1) * BK;
            int m0 = M0 + fm, m1 = M0 + fm + 128;
            hp0 = (m0 < N) ? *(const float4*)(hin + (size_t)m0 * H + k0n + 4 * fq) : make_float4(0, 0, 0, 0);
            hp1 = (m1 < N) ? *(const float4*)(hin + (size_t)m1 * H + k0n + 4 * fq) : make_float4(0, 0, 0, 0);
        }
        const float* wkbase = Ws + (size_t)it * BK * 64;
#pragma unroll
        for (int kk = 0; kk < BK; kk++) {
            const float* hbase = Hs + kk * RP + ty * 8;
            float4 ha = *(const float4*)hbase;
            float4 hb = *(const float4*)(hbase + 4);
            const float* w = wkbase + kk * 64;
            unsigned long long wv[4];
#pragma unroll
            for (int s = 0; s < 4; s++)
                wv[s] = *(const unsigned long long*)(w + 2 * tx + 16 * s);
            float hv[8] = {ha.x, ha.y, ha.z, ha.w, hb.x, hb.y, hb.z, hb.w};
#pragma unroll
            for (int r = 0; r < 8; r++) {
                unsigned long long hd = dup2(hv[r]);
                ffma2(acc[r][0], hd, wv[0]);
                ffma2(acc[r][1], hd, wv[1]);
                ffma2(acc[r][2], hd, wv[2]);
                ffma2(acc[r][3], hd, wv[3]);
            }
        }
        __syncthreads();
    }

#pragma unroll
    for (int s = 0; s < 4; s++) {
        int jb = J0 + 2 * tx + 16 * s;
        float bx = b[jb], by = b[jb + 1];
#pragma unroll
        for (int r = 0; r < 8; r++) {
            int m = M0 + ty * 8 + r;
            if (m < N) {
                float2 o;
                o.x = fmaxf(lo32(acc[r][s]) + bx, 0.0f);
                o.y = fmaxf(hi32(acc[r][s]) + by, 0.0f);
                *(float2*)(outp + (size_t)m * H + jb) = o;
            }
        }
    }
}

// ---------------------------------------------------------------------------
// y[:, t, :] = h @ out_W.T + out_b  (4 outputs; one warp per row)
// ---------------------------------------------------------------------------
__global__ void out_proj_kernel(const float* __restrict__ hin, const float* __restrict__ oW,
                                const float* __restrict__ ob, float* __restrict__ y,
                                int t, int PL, int N)
{
    int row  = blockIdx.x * 8 + (threadIdx.x >> 5);
    int lane = threadIdx.x & 31;
    if (row >= N) return;
    const float* hr = hin + (size_t)row * H;
    float a0 = 0.f, a1 = 0.f, a2 = 0.f, a3 = 0.f;
#pragma unroll
    for (int k = lane; k < H; k += 32) {
        float hv = hr[k];
        a0 += hv * oW[k];
        a1 += hv * oW[H + k];
        a2 += hv * oW[2 * H + k];
        a3 += hv * oW[3 * H + k];
    }
#pragma unroll
    for (int off = 16; off > 0; off >>= 1) {
        a0 += __shfl_down_sync(0xffffffffu, a0, off);
        a1 += __shfl_down_sync(0xffffffffu, a1, off);
        a2 += __shfl_down_sync(0xffffffffu, a2, off);
        a3 += __shfl_down_sync(0xffffffffu, a3, off);
    }
    if (lane == 0) {
        float4 r = make_float4(a0 + ob[0], a1 + ob[1], a2 + ob[2], a3 + ob[3]);
        *(float4*)(y + ((size_t)row * PL + t) * 4) = r;
    }
}

// ---------------------------------------------------------------------------
extern "C" void kernel_launch(void* const* d_in, const int* in_sizes, int n_in,
                              void* d_out, int out_size)
{
    const float* x    = (const float*)d_in[0];
    const float* embW = (const float*)d_in[1];
    const float* embB = (const float*)d_in[2];
    const float* eWih = (const float*)d_in[3];
    const float* eWhh = (const float*)d_in[4];
    const float* eBih = (const float*)d_in[5];
    const float* eBhh = (const float*)d_in[6];
    const float* dEW  = (const float*)d_in[7];
    const float* dEB  = (const float*)d_in[8];
    const float* dWih = (const float*)d_in[9];
    const float* dWhh = (const float*)d_in[10];
    const float* dBih = (const float*)d_in[11];
    const float* dBhh = (const float*)d_in[12];
    const float* oW   = (const float*)d_in[13];
    const float* oB   = (const float*)d_in[14];

    const int T = 15;
    int N = in_sizes[0] / (T * 4);
    if (N > MAXN) N = MAXN;
    int PL = out_size / (N * 4);
    float* y = (float*)d_out;

    float *hA, *hB, *din, *packE, *packD, *packL;
    cudaGetSymbolAddress((void**)&hA, g_hA);
    cudaGetSymbolAddress((void**)&hB, g_hB);
    cudaGetSymbolAddress((void**)&din, g_din);
    cudaGetSymbolAddress((void**)&packE, g_packE);
    cudaGetSymbolAddress((void**)&packD, g_packD);
    cudaGetSymbolAddress((void**)&packL, g_packL);

    const int GRU_SMEM = (2 * BK * RP + 256 * 192) * 4;   // 213,248 B
    const int LIN_SMEM = (BK * RP + 256 * 64) * 4;        //  73,856 B
    cudaFuncSetAttribute(gru2<true>,  cudaFuncAttributeMaxDynamicSharedMemorySize, GRU_SMEM);
    cudaFuncSetAttribute(gru2<false>, cudaFuncAttributeMaxDynamicSharedMemorySize, GRU_SMEM);
    cudaFuncSetAttribute(lin2,        cudaFuncAttributeMaxDynamicSharedMemorySize, LIN_SMEM);

    // pack weights (once per launch; inside the graph)
    {
        int total = 8 * 256 * 192 + 4 * 256 * 64;
        pack_kernel<<<(total + 255) / 256, 256>>>(eWih, eWhh, dWih, dWhh, dEW);
    }
    cudaMemsetAsync(hA, 0, (size_t)N * H * sizeof(float));

    dim3 gGrid((N + 255) / 256, 8);
    dim3 lGrid((N + 255) / 256, 4);
    dim3 blk(256);

    float* hc = hA;
    float* hn = hB;
    for (int t = 0; t < T; t++) {
        gru2<true><<<gGrid, blk, GRU_SMEM>>>(x, t, embW, embB, hc,
                                             packE, eBih, eBhh, hn, N);
        float* tmp = hc; hc = hn; hn = tmp;
    }
    lin2<<<lGrid, blk, LIN_SMEM>>>(hc, packL, dEB, din, N);
    for (int t = 0; t < PL; t++) {
        gru2<false><<<gGrid, blk, GRU_SMEM>>>(din, 0, (const float*)0, (const float*)0, hc,
                                              packD, dBih, dBhh, hn, N);
        float* tmp = hc; hc = hn; hn = tmp;
        out_proj_kernel<<<(N + 7) / 8, 256>>>(hc, oW, oB, y, t, PL, N);
        if (t + 1 < PL) lin2<<<lGrid, blk, LIN_SMEM>>>(hc, packL, dEB, din, N);
    }
}